// round 8
// baseline (speedup 1.0000x reference)
#include <cuda_runtime.h>
#include <math.h>

typedef unsigned long long u64;

// ---------------- shapes ----------------
#define BERT 768
#define CTRY 24
#define CODE 8
#define GAZ  9
#define MIX  24
#define NFEAT 13
#define CMAX 64
#define B_MAX 2048
#define NCTRY_MAX 512
#define NCODES_MAX 1024

// ---------------- device scratch ----------------
__device__ float g_cet  [NCTRY_MAX * CTRY];   // NORMALIZED projected country embs
__device__ float g_codeN[NCODES_MAX * CODE];  // NORMALIZED code embeddings
__device__ float g_proj [B_MAX * 80];         // x(24)|x_code(8)|x_other(24)|x_doc(24), raw

// ---------------- f32x2 helpers ----------------
__device__ __forceinline__ void ffma2(u64& d, u64 a, u64 b) {
    asm("fma.rn.f32x2 %0, %1, %2, %0;" : "+l"(d) : "l"(a), "l"(b));
}
__device__ __forceinline__ u64 pack2(float lo, float hi) {
    u64 r; asm("mov.b64 %0, {%1,%2};" : "=l"(r) : "f"(lo), "f"(hi)); return r;
}
__device__ __forceinline__ void unpack2(u64 v, float& lo, float& hi) {
    asm("mov.b64 {%0,%1}, %2;" : "=f"(lo), "=f"(hi) : "l"(v));
}
__device__ __forceinline__ float hsum2(u64 v) {
    float lo, hi; unpack2(v, lo, hi); return lo + hi;
}
__device__ __forceinline__ float sigf(float x) {
    float t; asm("tanh.approx.f32 %0, %1;" : "=f"(t) : "f"(x * 0.5f));
    return fmaf(0.5f, t, 0.5f);
}
__device__ __forceinline__ void pf_l2(const void* p) {
    asm volatile("prefetch.global.L2 [%0];" :: "l"(p));
}

#define PF_BLOCKS 16

// =====================================================================
// k_pre grid: [0,PF) L2-prefetch | [PF,PF+PB) proj (8 rows/blk) |
//             [.., +CB) cet (4/blk, normalized) | rest: codeN
// proj: 256 thr = 4 row-pairs x 64 k-slices(12); weights double-buffered
// in SMEM; ctx passes feed other+doc simultaneously (7 passes total).
// =====================================================================
__global__ void __launch_bounds__(256, 2) k_pre(
    const float* __restrict__ place, const float* __restrict__ other,
    const float* __restrict__ doc,
    const float* __restrict__ Wt2c, const float* __restrict__ bt2c,
    const float* __restrict__ Wcode, const float* __restrict__ bcode,
    const float* __restrict__ Wctx, const float* __restrict__ bctx,
    const float* __restrict__ cemb, const float* __restrict__ Wcet,
    const float* __restrict__ bcet, const float* __restrict__ codeTab,
    const int* __restrict__ fcodes, const int* __restrict__ ccodes,
    const float* __restrict__ gaz,
    int PB, int CB, int nCtry, int nCodes, int Bn)
{
    __shared__ __align__(16) float sW[2][8 * BERT];   // 2 x 24KB
    __shared__ float sred[8 * 132 + 8];
    const int bid  = blockIdx.x;
    const int tid  = threadIdx.x;
    const int warp = tid >> 5, lane = tid & 31;

    if (bid < PF_BLOCKS) {
        // ---------------- L2 prefetch of k_mlp's inputs ----------------
        const int PFT = PF_BLOCKS * 256;
        int t = bid * 256 + tid;
        int gl = (Bn * CMAX * GAZ * 4 + 127) >> 7;
        for (int j = t; j < gl; j += PFT)
            pf_l2((const char*)gaz + ((size_t)j << 7));
        int cl = (Bn * CMAX * 4 + 127) >> 7;
        for (int j = t; j < cl; j += PFT) {
            pf_l2((const char*)fcodes + ((size_t)j << 7));
            pf_l2((const char*)ccodes + ((size_t)j << 7));
        }
        return;
    }

    if (bid < PF_BLOCKS + PB) {
        const int rg   = lane & 3;                  // row-pair 0..3
        const int ksl  = (warp << 3) | (lane >> 2); // k-slice 0..63
        const int koff = ksl * 12;
        const int row0 = (bid - PF_BLOCKS) * 8;
        const int rA = min(row0 + rg * 2,     Bn - 1);
        const int rB = min(row0 + rg * 2 + 1, Bn - 1);

        u64 xPA[6], xPB[6], xOA[6], xOB[6], xDA[6], xDB[6];
        #define LDX(dst, src, r) { \
            const ulonglong2* p_ = (const ulonglong2*)((src) + (size_t)(r) * BERT + koff); \
            ulonglong2 v0 = __ldg(p_), v1 = __ldg(p_ + 1), v2 = __ldg(p_ + 2);            \
            dst[0]=v0.x; dst[1]=v0.y; dst[2]=v1.x; dst[3]=v1.y; dst[4]=v2.x; dst[5]=v2.y; }
        LDX(xPA, place, rA); LDX(xPB, place, rB);
        LDX(xOA, other, rA); LDX(xOB, other, rB);
        LDX(xDA, doc,   rA); LDX(xDB, doc,   rB);
        #undef LDX

        float4 wst[6];
        {   // stage pass-0 weights (Wt2c rows 0..7)
            const float4* src = (const float4*)Wt2c;
            #pragma unroll
            for (int j = 0; j < 6; j++) wst[j] = __ldg(src + tid + j * 256);
            float4* dst = (float4*)sW[0];
            #pragma unroll
            for (int j = 0; j < 6; j++) dst[tid + j * 256] = wst[j];
        }
        __syncthreads();

        int cur = 0;
        #pragma unroll 1
        for (int bb = 0; bb < 7; bb++) {
            if (bb < 6) {   // prefetch next weight tile into regs
                int nb = bb + 1;
                const float* Wn = (nb < 3)  ? Wt2c + nb * 8 * BERT
                                : (nb == 3) ? Wcode
                                :             Wctx + (nb - 4) * 8 * BERT;
                const float4* src = (const float4*)Wn;
                #pragma unroll
                for (int j = 0; j < 6; j++) wst[j] = __ldg(src + tid + j * 256);
            }
            const float* Wsm = sW[cur];

            if (bb < 4) {
                // ---- place-driven passes (t2c x3, code x1) ----
                float rA8[8], rB8[8];
                #pragma unroll
                for (int ob = 0; ob < 8; ob++) {
                    const ulonglong2* w = (const ulonglong2*)(Wsm + ob * BERT + koff);
                    u64 sA = 0ull, sB = 0ull;
                    #pragma unroll
                    for (int j = 0; j < 3; j++) {
                        ulonglong2 wv = w[j];
                        ffma2(sA, xPA[2*j], wv.x); ffma2(sA, xPA[2*j+1], wv.y);
                        ffma2(sB, xPB[2*j], wv.x); ffma2(sB, xPB[2*j+1], wv.y);
                    }
                    float a = hsum2(sA), b = hsum2(sB);
                    a += __shfl_xor_sync(0xffffffffu, a, 4);
                    a += __shfl_xor_sync(0xffffffffu, a, 8);
                    a += __shfl_xor_sync(0xffffffffu, a, 16);
                    b += __shfl_xor_sync(0xffffffffu, b, 4);
                    b += __shfl_xor_sync(0xffffffffu, b, 8);
                    b += __shfl_xor_sync(0xffffffffu, b, 16);
                    rA8[ob] = a; rB8[ob] = b;
                }
                if (lane < 4) {
                    float* p = sred + warp * 132 + rg * 16;
                    #pragma unroll
                    for (int ob = 0; ob < 8; ob++) { p[ob] = rA8[ob]; p[8 + ob] = rB8[ob]; }
                }
                __syncthreads();
                if (bb < 6) {
                    float4* dst = (float4*)sW[cur ^ 1];
                    #pragma unroll
                    for (int j = 0; j < 6; j++) dst[tid + j * 256] = wst[j];
                }
                if (tid < 64) {
                    int rr = tid >> 3, ob = tid & 7;
                    float a = 0.f;
                    #pragma unroll
                    for (int w2 = 0; w2 < 8; w2++)
                        a += sred[w2 * 132 + (rr >> 1) * 16 + (rr & 1) * 8 + ob];
                    if (row0 + rr < Bn) {
                        int seg = (bb < 3) ? bb * 8 : 24;
                        float bias = (bb < 3) ? bt2c[bb * 8 + ob] : bcode[ob];
                        g_proj[(row0 + rr) * 80 + seg + ob] = a + bias;
                    }
                }
            } else {
                // ---- ctx passes: other + doc share this weight tile ----
                float oA8[8], oB8[8], dA8[8], dB8[8];
                #pragma unroll
                for (int ob = 0; ob < 8; ob++) {
                    const ulonglong2* w = (const ulonglong2*)(Wsm + ob * BERT + koff);
                    u64 so = 0ull, sp = 0ull, sq = 0ull, sr = 0ull;
                    #pragma unroll
                    for (int j = 0; j < 3; j++) {
                        ulonglong2 wv = w[j];
                        ffma2(so, xOA[2*j], wv.x); ffma2(so, xOA[2*j+1], wv.y);
                        ffma2(sp, xOB[2*j], wv.x); ffma2(sp, xOB[2*j+1], wv.y);
                        ffma2(sq, xDA[2*j], wv.x); ffma2(sq, xDA[2*j+1], wv.y);
                        ffma2(sr, xDB[2*j], wv.x); ffma2(sr, xDB[2*j+1], wv.y);
                    }
                    float a = hsum2(so), b = hsum2(sp), c = hsum2(sq), d = hsum2(sr);
                    #pragma unroll
                    for (int o = 4; o <= 16; o <<= 1) {
                        a += __shfl_xor_sync(0xffffffffu, a, o);
                        b += __shfl_xor_sync(0xffffffffu, b, o);
                        c += __shfl_xor_sync(0xffffffffu, c, o);
                        d += __shfl_xor_sync(0xffffffffu, d, o);
                    }
                    oA8[ob] = a; oB8[ob] = b; dA8[ob] = c; dB8[ob] = d;
                }
                if (lane < 4) {
                    float* p = sred + warp * 132 + rg * 32;
                    #pragma unroll
                    for (int ob = 0; ob < 8; ob++) {
                        p[ob] = oA8[ob]; p[8 + ob] = oB8[ob];
                        p[16 + ob] = dA8[ob]; p[24 + ob] = dB8[ob];
                    }
                }
                __syncthreads();
                if (bb < 6) {
                    float4* dst = (float4*)sW[cur ^ 1];
                    #pragma unroll
                    for (int j = 0; j < 6; j++) dst[tid + j * 256] = wst[j];
                }
                {
                    int od = tid >> 7;            // 0=other, 1=doc
                    int rr = (tid >> 4) & 7;      // wait: need tid<128 mapping
                }
                if (tid < 128) {
                    int od = tid >> 6;            // 0=other, 1=doc
                    int rr = (tid >> 3) & 7;
                    int ob = tid & 7;
                    float a = 0.f;
                    #pragma unroll
                    for (int w2 = 0; w2 < 8; w2++)
                        a += sred[w2 * 132 + (rr >> 1) * 32 + od * 16 + (rr & 1) * 8 + ob];
                    if (row0 + rr < Bn) {
                        int wr0 = (bb - 4) * 8;
                        g_proj[(row0 + rr) * 80 + 32 + od * 24 + wr0 + ob] = a + bctx[wr0 + ob];
                    }
                }
            }
            __syncthreads();
            cur ^= 1;
        }
    } else if (bid < PF_BLOCKS + PB + CB) {
        // ---------- cet projection + NORMALIZE, 4 countries / block ----------
        float* sv = sred;
        const int i0 = (bid - PF_BLOCKS - PB) * 4;
        #pragma unroll 1
        for (int t4 = 0; t4 < 4; t4++) {
            int i = i0 + t4;
            if (i < nCtry) {
                const float* e = cemb + (size_t)i * BERT;
                #pragma unroll
                for (int t = 0; t < 3; t++) {
                    int j = warp * 3 + t;
                    const float* w = Wcet + (size_t)j * BERT;
                    float a = 0.f;
                    #pragma unroll
                    for (int q = 0; q < 6; q++) {
                        int k = lane * 4 + q * 128;
                        float4 ev = *(const float4*)(e + k);
                        float4 wv = __ldg((const float4*)(w + k));
                        a += ev.x * wv.x + ev.y * wv.y + ev.z * wv.z + ev.w * wv.w;
                    }
                    #pragma unroll
                    for (int o = 16; o; o >>= 1) a += __shfl_xor_sync(0xffffffffu, a, o);
                    if (lane == 0) sv[j] = a + bcet[j];
                }
            }
            __syncthreads();
            if (i < nCtry && tid < 32) {
                float v = (lane < CTRY) ? sv[lane] : 0.f;
                float s = v * v;
                #pragma unroll
                for (int o = 16; o; o >>= 1) s += __shfl_xor_sync(0xffffffffu, s, o);
                float rinv = __fdividef(1.f, fmaxf(sqrtf(s), 1e-8f));
                if (lane < CTRY) g_cet[i * CTRY + lane] = v * rinv;
            }
            __syncthreads();
        }
    } else {
        // ---------- normalized code embeddings ----------
        int i = (bid - PF_BLOCKS - PB - CB) * 256 + tid;
        if (i < nCodes) {
            float s = 0.f;
            float v[CODE];
            #pragma unroll
            for (int j = 0; j < CODE; j++) { v[j] = codeTab[i * CODE + j]; s += v[j] * v[j]; }
            float rinv = __fdividef(1.f, fmaxf(sqrtf(s), 1e-8f));
            #pragma unroll
            for (int j = 0; j < CODE; j++) g_codeN[i * CODE + j] = v[j] * rinv;
        }
    }
}

// =====================================================================
// k_mlp: 128 thr = 4 rows x 32 lanes; lane handles candidates c, c+32.
// sX rows pre-normalized once -> cosines are raw dots, no divisions.
// =====================================================================
__global__ void __launch_bounds__(128, 5) k_mlp(
    const int* __restrict__ fcodes, const int* __restrict__ ccodes,
    const float* __restrict__ gaz,
    const float* __restrict__ W1, const float* __restrict__ b1,
    const float* __restrict__ W2, const float* __restrict__ b2,
    const float* __restrict__ WL, const float* __restrict__ bL,
    float* __restrict__ out, int Bn)
{
    __shared__ __align__(16) float sW1T[NFEAT * MIX];
    __shared__ __align__(16) float sW2[MIX * MIX];
    __shared__ __align__(16) float sB1[MIX];
    __shared__ float sB2[MIX], sWL[MIX];
    __shared__ __align__(16) float sGaz[4 * CMAX * GAZ];
    __shared__ __align__(16) float sX[4 * 80];
    __shared__ float sNi[4][4];
    __shared__ float sbL;

    const int tid = threadIdx.x;
    const int b0  = blockIdx.x * 4;

    for (int i = tid; i < NFEAT * MIX; i += 128) {
        int q = i / MIX, j = i - q * MIX;
        sW1T[i] = W1[j * NFEAT + q];
    }
    for (int i = tid; i < MIX * MIX; i += 128) sW2[i] = W2[i];
    if (tid < MIX) { sB1[tid] = b1[tid]; sB2[tid] = b2[tid]; sWL[tid] = WL[tid]; }
    if (tid == 0) sbL = bL[0];
    {
        int cnt = min(576, (Bn - b0) * 144);
        const float4* gp = (const float4*)gaz + (size_t)b0 * 144;
        float4* sp = (float4*)sGaz;
        for (int i = tid; i < cnt; i += 128) sp[i] = __ldg(gp + i);
    }
    for (int i = tid; i < 4 * 80; i += 128) {
        int bb = min(b0 + i / 80, Bn - 1);
        sX[i] = g_proj[bb * 80 + (i % 80)];
    }
    __syncthreads();

    if (tid < 16) {
        int gg = tid >> 2, which = tid & 3;
        int off = (which == 0) ? 0 : (which == 1) ? 24 : (which == 2) ? 32 : 56;
        int cnt = (which == 1) ? CODE : CTRY;
        float ss = 0.f;
        for (int j = 0; j < cnt; j++) { float v = sX[gg * 80 + off + j]; ss += v * v; }
        sNi[gg][which] = __fdividef(1.f, fmaxf(sqrtf(ss), 1e-8f));
    }
    __syncthreads();
    for (int i = tid; i < 4 * 80; i += 128) {
        int r = i / 80, o = i - r * 80;
        int seg = (o < 24) ? 0 : (o < 32) ? 1 : (o < 56) ? 2 : 3;
        sX[i] *= sNi[r][seg];
    }
    __syncthreads();

    const int g    = tid >> 5;
    const int lane = tid & 31;
    const int b    = min(b0 + g, Bn - 1);
    const int idx0 = b * CMAX + lane;
    const int idx1 = idx0 + 32;
    const int fc0 = fcodes[idx0], cc0 = ccodes[idx0];
    const int fc1 = fcodes[idx1], cc1 = ccodes[idx1];
    const float* sx = sX + g * 80;

    const ulonglong2* cet0 = (const ulonglong2*)(g_cet + cc0 * CTRY);
    const ulonglong2* cet1 = (const ulonglong2*)(g_cet + cc1 * CTRY);
    const u64* x1 = (const u64*)(sx);
    const u64* x3 = (const u64*)(sx + 32);
    const u64* x4 = (const u64*)(sx + 56);
    u64 p10=0, p30=0, p40=0, p11=0, p31=0, p41=0;
    #pragma unroll
    for (int j = 0; j < 6; j++) {
        ulonglong2 c0 = __ldg(cet0 + j);
        ulonglong2 c1 = __ldg(cet1 + j);
        u64 xa = x1[2*j], xb = x1[2*j+1];
        ffma2(p10, xa, c0.x); ffma2(p10, xb, c0.y);
        ffma2(p11, xa, c1.x); ffma2(p11, xb, c1.y);
        xa = x3[2*j]; xb = x3[2*j+1];
        ffma2(p30, xa, c0.x); ffma2(p30, xb, c0.y);
        ffma2(p31, xa, c1.x); ffma2(p31, xb, c1.y);
        xa = x4[2*j]; xb = x4[2*j+1];
        ffma2(p40, xa, c0.x); ffma2(p40, xb, c0.y);
        ffma2(p41, xa, c1.x); ffma2(p41, xb, c1.y);
    }
    const ulonglong2* fe0 = (const ulonglong2*)(g_codeN + fc0 * CODE);
    const ulonglong2* fe1 = (const ulonglong2*)(g_codeN + fc1 * CODE);
    const u64* x2p = (const u64*)(sx + 24);
    u64 p20 = 0, p21 = 0;
    #pragma unroll
    for (int j = 0; j < 2; j++) {
        ulonglong2 c0 = __ldg(fe0 + j);
        ulonglong2 c1 = __ldg(fe1 + j);
        u64 xa = x2p[2*j], xb = x2p[2*j+1];
        ffma2(p20, xa, c0.x); ffma2(p20, xb, c0.y);
        ffma2(p21, xa, c1.x); ffma2(p21, xb, c1.y);
    }
    float feat0[4], feat1[4];
    feat0[0] = hsum2(p10); feat0[1] = hsum2(p20);
    feat0[2] = hsum2(p30); feat0[3] = hsum2(p40);
    feat1[0] = hsum2(p11); feat1[1] = hsum2(p21);
    feat1[2] = hsum2(p31); feat1[3] = hsum2(p41);

    // ---- layer 1 ----
    u64 a0[12], a1[12];
    const u64* b1p = (const u64*)sB1;
    #pragma unroll
    for (int j = 0; j < 12; j++) { a0[j] = b1p[j]; a1[j] = b1p[j]; }

    const float* gz0 = sGaz + ((g * CMAX) + lane) * GAZ;
    const float* gz1 = gz0 + 32 * GAZ;
    #pragma unroll
    for (int q = 0; q < NFEAT; q++) {
        float f0 = (q < 4) ? feat0[q] : gz0[q - 4];
        float f1 = (q < 4) ? feat1[q] : gz1[q - 4];
        u64 ff0 = pack2(f0, f0), ff1 = pack2(f1, f1);
        const ulonglong2* wc = (const ulonglong2*)(sW1T + q * MIX);
        #pragma unroll
        for (int j2 = 0; j2 < 6; j2++) {
            ulonglong2 wv = wc[j2];
            ffma2(a0[2*j2],   ff0, wv.x); ffma2(a0[2*j2+1], ff0, wv.y);
            ffma2(a1[2*j2],   ff1, wv.x); ffma2(a1[2*j2+1], ff1, wv.y);
        }
    }
    #pragma unroll
    for (int j = 0; j < 12; j++) {
        float lo, hi;
        unpack2(a0[j], lo, hi); a0[j] = pack2(sigf(lo), sigf(hi));
        unpack2(a1[j], lo, hi); a1[j] = pack2(sigf(lo), sigf(hi));
    }

    // ---- layer 2 + last ----
    float last0 = sbL, last1 = sbL;
    #pragma unroll
    for (int j = 0; j < MIX; j++) {
        const ulonglong2* wr = (const ulonglong2*)(sW2 + j * MIX);
        u64 s0 = 0ull, s1 = 0ull;
        #pragma unroll
        for (int q2 = 0; q2 < 6; q2++) {
            ulonglong2 wv = wr[q2];
            ffma2(s0, a0[2*q2],   wv.x); ffma2(s0, a0[2*q2+1], wv.y);
            ffma2(s1, a1[2*q2],   wv.x); ffma2(s1, a1[2*q2+1], wv.y);
        }
        float v0 = sB2[j] + hsum2(s0);
        float v1 = sB2[j] + hsum2(s1);
        last0 = fmaf(sWL[j], sigf(v0), last0);
        last1 = fmaf(sWL[j], sigf(v1), last1);
    }

    // ---- warp softmax over 64 candidates ----
    float m = fmaxf(last0, last1);
    #pragma unroll
    for (int o = 16; o; o >>= 1) m = fmaxf(m, __shfl_xor_sync(0xffffffffu, m, o));
    float e0 = __expf(last0 - m);
    float e1 = __expf(last1 - m);
    float ss = e0 + e1;
    #pragma unroll
    for (int o = 16; o; o >>= 1) ss += __shfl_xor_sync(0xffffffffu, ss, o);
    float inv = __fdividef(1.f, ss);
    if (b0 + g < Bn) {
        out[idx0] = e0 * inv;
        out[idx1] = e1 * inv;
    }
}

// =====================================================================
extern "C" void kernel_launch(void* const* d_in, const int* in_sizes, int n_in,
                              void* d_out, int out_size)
{
    const float* place  = (const float*)d_in[0];
    const float* other  = (const float*)d_in[1];
    const float* doc    = (const float*)d_in[2];
    const int*   fcodes = (const int*)  d_in[3];
    const int*   ccodes = (const int*)  d_in[4];
    const float* gaz    = (const float*)d_in[5];
    const float* codeTab= (const float*)d_in[6];
    const float* ctryTab= (const float*)d_in[7];
    const float* Wcet   = (const float*)d_in[8];
    const float* bcet   = (const float*)d_in[9];
    const float* Wt2c   = (const float*)d_in[10];
    const float* bt2c   = (const float*)d_in[11];
    const float* Wctx   = (const float*)d_in[12];
    const float* bctx   = (const float*)d_in[13];
    const float* Wcode  = (const float*)d_in[14];
    const float* bcode  = (const float*)d_in[15];
    const float* W1     = (const float*)d_in[16];
    const float* b1     = (const float*)d_in[17];
    const float* W2     = (const float*)d_in[18];
    const float* b2     = (const float*)d_in[19];
    const float* WL     = (const float*)d_in[20];
    const float* bL     = (const float*)d_in[21];
    float* out = (float*)d_out;

    int B      = in_sizes[0] / BERT;
    int nCtry  = in_sizes[7] / BERT;
    int nCodes = in_sizes[6] / CODE;

    int PB = (B + 7) / 8;
    int CB = (nCtry + 3) / 4;
    int grid = PF_BLOCKS + PB + CB + (nCodes + 255) / 256;

    k_pre<<<grid, 256>>>(place, other, doc,
                         Wt2c, bt2c, Wcode, bcode, Wctx, bctx,
                         ctryTab, Wcet, bcet, codeTab,
                         fcodes, ccodes, gaz,
                         PB, CB, nCtry, nCodes, B);
    k_mlp<<<(B + 3) / 4, 128>>>(fcodes, ccodes, gaz,
                                W1, b1, W2, b2, WL, bL, out, B);
}